// round 1
// baseline (speedup 1.0000x reference)
#include <cuda_runtime.h>
#include <cuda_bf16.h>
#include <math.h>

// Problem constants (fixed by setup_inputs)
#define B       32
#define HQ      32
#define HKV     8
#define G       4      // HQ / HKV
#define D       128
#define BS      16     // block_size
#define MAXB    256    // max_blocks
#define CHUNK   256    // tokens per split
#define NS      16     // max splits = 4096 / CHUNK
#define NWARP   8

#define QSCALE  (0.08838834764831845f * 1.4426950408889634f)  // SCALE * log2(e)
#define NEG_BIG (-1e30f)

// Scratch: partial (unnormalized) outputs + log-domain stats per (b, hkv, split, g)
__device__ float g_part_acc[B * HKV * NS * G * D];   // 8 MB
__device__ float g_part_m  [B * HKV * NS * G];
__device__ float g_part_l  [B * HKV * NS * G];

__global__ __launch_bounds__(256, 4)
void attn_split_kernel(const float* __restrict__ q,
                       const float* __restrict__ kc,
                       const float* __restrict__ vc,
                       const int*   __restrict__ seqlens,
                       const int*   __restrict__ btab)
{
    const int b  = blockIdx.x;
    const int h  = blockIdx.y;
    const int sp = blockIdx.z;

    const int L     = seqlens[b];
    const int start = sp * CHUNK;
    if (start >= L) return;
    const int end = min(start + CHUNK, L);

    const int lane = threadIdx.x & 31;
    const int w    = threadIdx.x >> 5;

    // Load q for the G heads of this kv-head, pre-scaled into log2 domain.
    float4 q4[G];
    const float* qb = q + ((b * HQ) + h * G) * D + lane * 4;
#pragma unroll
    for (int g = 0; g < G; g++) {
        float4 t = *(const float4*)(qb + g * D);
        q4[g].x = t.x * QSCALE;
        q4[g].y = t.y * QSCALE;
        q4[g].z = t.z * QSCALE;
        q4[g].w = t.w * QSCALE;
    }

    float  m[G], l[G];
    float4 acc[G];
#pragma unroll
    for (int g = 0; g < G; g++) {
        m[g] = NEG_BIG; l[g] = 0.f;
        acc[g].x = acc[g].y = acc[g].z = acc[g].w = 0.f;
    }

    const int* bt = btab + b * MAXB;

    for (int t = start + w; t < end; t += NWARP) {
        const int blk  = bt[t >> 4];
        const int roff = ((blk * BS + (t & 15)) * HKV + h) * D + lane * 4;
        const float4 k4 = *(const float4*)(kc + roff);
        const float4 v4 = *(const float4*)(vc + roff);

#pragma unroll
        for (int g = 0; g < G; g++) {
            float s = q4[g].x * k4.x + q4[g].y * k4.y
                    + q4[g].z * k4.z + q4[g].w * k4.w;
            s += __shfl_xor_sync(0xffffffffu, s, 16);
            s += __shfl_xor_sync(0xffffffffu, s, 8);
            s += __shfl_xor_sync(0xffffffffu, s, 4);
            s += __shfl_xor_sync(0xffffffffu, s, 2);
            s += __shfl_xor_sync(0xffffffffu, s, 1);

            const float mn    = fmaxf(m[g], s);
            const float alpha = exp2f(m[g] - mn);
            const float p     = exp2f(s - mn);
            m[g] = mn;
            l[g] = l[g] * alpha + p;
            acc[g].x = acc[g].x * alpha + p * v4.x;
            acc[g].y = acc[g].y * alpha + p * v4.y;
            acc[g].z = acc[g].z * alpha + p * v4.z;
            acc[g].w = acc[g].w * alpha + p * v4.w;
        }
    }

    // CTA-level merge of 8 warp partials
    __shared__ float sm[NWARP][G];
    __shared__ float sl[NWARP][G];
    __shared__ float sacc[NWARP][G][D];

#pragma unroll
    for (int g = 0; g < G; g++) {
        sm[w][g] = m[g];
        sl[w][g] = l[g];
        *(float4*)&sacc[w][g][lane * 4] = acc[g];
    }
    __syncthreads();

    if (w < G) {
        const int g = w;
        float M = NEG_BIG;
#pragma unroll
        for (int ww = 0; ww < NWARP; ww++) M = fmaxf(M, sm[ww][g]);

        float Lsum = 0.f;
        float4 o = {0.f, 0.f, 0.f, 0.f};
#pragma unroll
        for (int ww = 0; ww < NWARP; ww++) {
            const float e = exp2f(sm[ww][g] - M);
            Lsum += e * sl[ww][g];
            const float4 a = *(const float4*)&sacc[ww][g][lane * 4];
            o.x += e * a.x; o.y += e * a.y; o.z += e * a.z; o.w += e * a.w;
        }

        const int idx = (((b * HKV + h) * NS + sp) * G + g);
        if (lane == 0) {
            g_part_m[idx] = M;
            g_part_l[idx] = Lsum;
        }
        *(float4*)&g_part_acc[idx * D + lane * 4] = o;
    }
}

__global__ __launch_bounds__(128)
void attn_combine_kernel(const int* __restrict__ seqlens,
                         float* __restrict__ out)
{
    const int bh = blockIdx.x;          // b * HQ + hq
    const int b  = bh / HQ;
    const int hq = bh % HQ;
    const int h  = hq / G;
    const int g  = hq % G;
    const int d  = threadIdx.x;

    const int L   = seqlens[b];
    const int nsp = min(NS, (L + CHUNK - 1) / CHUNK);

    const int base = ((b * HKV + h) * NS) * G + g;  // + sp*G per split

    float M = NEG_BIG;
    for (int sp = 0; sp < nsp; sp++)
        M = fmaxf(M, g_part_m[base + sp * G]);

    float Lsum = 0.f, o = 0.f;
    for (int sp = 0; sp < nsp; sp++) {
        const int idx = base + sp * G;
        const float e = exp2f(g_part_m[idx] - M);
        Lsum += e * g_part_l[idx];
        o    += e * g_part_acc[idx * D + d];
    }

    out[bh * D + d] = o / Lsum;
}

extern "C" void kernel_launch(void* const* d_in, const int* in_sizes, int n_in,
                              void* d_out, int out_size)
{
    const float* q   = (const float*)d_in[0];
    const float* kc  = (const float*)d_in[1];
    const float* vc  = (const float*)d_in[2];
    const int*   sl  = (const int*)  d_in[3];
    const int*   bt  = (const int*)  d_in[4];
    float*       out = (float*)d_out;

    dim3 grid1(B, HKV, NS);
    attn_split_kernel<<<grid1, 256>>>(q, kc, vc, sl, bt);
    attn_combine_kernel<<<B * HQ, 128>>>(sl, out);
}

// round 3
// speedup vs baseline: 1.0552x; 1.0552x over previous
#include <cuda_runtime.h>
#include <cuda_bf16.h>
#include <math.h>

// Problem constants (fixed by setup_inputs)
#define B       32
#define HQ      32
#define HKV     8
#define G       4      // HQ / HKV
#define D       128
#define BS      16     // block_size
#define MAXB    256    // max_blocks
#define CHUNK   256    // tokens per split
#define NS      16     // max splits = 4096 / CHUNK
#define NWARP   8

#define QSCALE  (0.08838834764831845f * 1.4426950408889634f)  // SCALE * log2(e)
#define NEG_BIG (-1e30f)
#define FULLM   0xffffffffu

// Scratch: partial (unnormalized) outputs + log-domain stats per (b, hkv, split, g)
__device__ float g_part_acc[B * HKV * NS * G * D];   // 8 MB
__device__ float g_part_m  [B * HKV * NS * G];
__device__ float g_part_l  [B * HKV * NS * G];

__global__ __launch_bounds__(256, 3)
void attn_split_kernel(const float* __restrict__ q,
                       const float* __restrict__ kc,
                       const float* __restrict__ vc,
                       const int*   __restrict__ seqlens,
                       const int*   __restrict__ btab)
{
    const int b  = blockIdx.x;
    const int h  = blockIdx.y;
    const int sp = blockIdx.z;

    const int L     = seqlens[b];
    const int start = sp * CHUNK;
    if (start >= L) return;
    const int end = min(start + CHUNK, L);

    const int lane = threadIdx.x & 31;
    const int w    = threadIdx.x >> 5;

    // Load q for the G heads of this kv-head, pre-scaled into log2 domain.
    float4 q4[G];
    const float* qb = q + ((b * HQ) + h * G) * D + lane * 4;
#pragma unroll
    for (int g = 0; g < G; g++) {
        float4 t = *(const float4*)(qb + g * D);
        q4[g].x = t.x * QSCALE;
        q4[g].y = t.y * QSCALE;
        q4[g].z = t.z * QSCALE;
        q4[g].w = t.w * QSCALE;
    }

    float  m[G], l[G];
    float4 acc[G];
#pragma unroll
    for (int g = 0; g < G; g++) {
        m[g] = NEG_BIG; l[g] = 0.f;
        acc[g].x = acc[g].y = acc[g].z = acc[g].w = 0.f;
    }

    const int* bt = btab + b * MAXB;

    // merged 4-head warp reduction: 9 shfl reduce + 4 broadcast (vs 20)
    auto reduce4 = [&](float s0, float s1, float s2, float s3,
                       float& t0, float& t1, float& t2, float& t3) {
        float u0 = __shfl_xor_sync(FULLM, s0, 16);
        float u1 = __shfl_xor_sync(FULLM, s1, 16);
        float u2 = __shfl_xor_sync(FULLM, s2, 16);
        float u3 = __shfl_xor_sync(FULLM, s3, 16);
        float p01 = (lane & 16) ? (s1 + u1) : (s0 + u0);
        float p23 = (lane & 16) ? (s3 + u3) : (s2 + u2);
        float v01 = __shfl_xor_sync(FULLM, p01, 8);
        float v23 = __shfl_xor_sync(FULLM, p23, 8);
        float r = (lane & 8) ? (p23 + v23) : (p01 + v01);
        r += __shfl_xor_sync(FULLM, r, 4);
        r += __shfl_xor_sync(FULLM, r, 2);
        r += __shfl_xor_sync(FULLM, r, 1);
        // quarter->head map: lanes0-7:h0, 8-15:h2, 16-23:h1, 24-31:h3
        t0 = __shfl_sync(FULLM, r, 0);
        t2 = __shfl_sync(FULLM, r, 8);
        t1 = __shfl_sync(FULLM, r, 16);
        t3 = __shfl_sync(FULLM, r, 24);
    };

    auto update = [&](int g, float s, const float4& v4) {
        if (s > m[g]) {                       // warp-uniform, rare (~ln(256) times)
            const float alpha = exp2f(m[g] - s);
            m[g] = s;
            l[g] = l[g] * alpha + 1.f;        // p = exp2(0) = 1
            acc[g].x = acc[g].x * alpha + v4.x;
            acc[g].y = acc[g].y * alpha + v4.y;
            acc[g].z = acc[g].z * alpha + v4.z;
            acc[g].w = acc[g].w * alpha + v4.w;
        } else {
            const float p = exp2f(s - m[g]);
            l[g] += p;
            acc[g].x += p * v4.x;
            acc[g].y += p * v4.y;
            acc[g].z += p * v4.z;
            acc[g].w += p * v4.w;
        }
    };

    for (int t = start + w; t < end; t += 2 * NWARP) {
        const int t2   = t + NWARP;
        const bool has2 = (t2 < end);

        // issue both tokens' loads up front (MLP = 4 LDG.128 + 2 scalar)
        const int blkA  = bt[t >> 4];
        const int offA  = ((blkA * BS + (t & 15)) * HKV + h) * D + lane * 4;
        const float4 kA = *(const float4*)(kc + offA);
        const float4 vA = *(const float4*)(vc + offA);

        float4 kB, vB;
        if (has2) {
            const int blkB = bt[t2 >> 4];
            const int offB = ((blkB * BS + (t2 & 15)) * HKV + h) * D + lane * 4;
            kB = *(const float4*)(kc + offB);
            vB = *(const float4*)(vc + offB);
        }

        {
            float s0 = q4[0].x*kA.x + q4[0].y*kA.y + q4[0].z*kA.z + q4[0].w*kA.w;
            float s1 = q4[1].x*kA.x + q4[1].y*kA.y + q4[1].z*kA.z + q4[1].w*kA.w;
            float s2 = q4[2].x*kA.x + q4[2].y*kA.y + q4[2].z*kA.z + q4[2].w*kA.w;
            float s3 = q4[3].x*kA.x + q4[3].y*kA.y + q4[3].z*kA.z + q4[3].w*kA.w;
            float t0, t1, t2s, t3;
            reduce4(s0, s1, s2, s3, t0, t1, t2s, t3);
            update(0, t0, vA); update(1, t1, vA);
            update(2, t2s, vA); update(3, t3, vA);
        }
        if (has2) {
            float s0 = q4[0].x*kB.x + q4[0].y*kB.y + q4[0].z*kB.z + q4[0].w*kB.w;
            float s1 = q4[1].x*kB.x + q4[1].y*kB.y + q4[1].z*kB.z + q4[1].w*kB.w;
            float s2 = q4[2].x*kB.x + q4[2].y*kB.y + q4[2].z*kB.z + q4[2].w*kB.w;
            float s3 = q4[3].x*kB.x + q4[3].y*kB.y + q4[3].z*kB.z + q4[3].w*kB.w;
            float t0, t1, t2s, t3;
            reduce4(s0, s1, s2, s3, t0, t1, t2s, t3);
            update(0, t0, vB); update(1, t1, vB);
            update(2, t2s, vB); update(3, t3, vB);
        }
    }

    // CTA-level merge of 8 warp partials
    __shared__ float sm[NWARP][G];
    __shared__ float sl[NWARP][G];
    __shared__ float sacc[NWARP][G][D];

#pragma unroll
    for (int g = 0; g < G; g++) {
        sm[w][g] = m[g];
        sl[w][g] = l[g];
        *(float4*)&sacc[w][g][lane * 4] = acc[g];
    }
    __syncthreads();

    if (w < G) {
        const int g = w;
        float M = NEG_BIG;
#pragma unroll
        for (int ww = 0; ww < NWARP; ww++) M = fmaxf(M, sm[ww][g]);

        float Lsum = 0.f;
        float4 o = {0.f, 0.f, 0.f, 0.f};
#pragma unroll
        for (int ww = 0; ww < NWARP; ww++) {
            const float e = exp2f(sm[ww][g] - M);
            Lsum += e * sl[ww][g];
            const float4 a = *(const float4*)&sacc[ww][g][lane * 4];
            o.x += e * a.x; o.y += e * a.y; o.z += e * a.z; o.w += e * a.w;
        }

        const int idx = (((b * HKV + h) * NS + sp) * G + g);
        if (lane == 0) {
            g_part_m[idx] = M;
            g_part_l[idx] = Lsum;
        }
        *(float4*)&g_part_acc[idx * D + lane * 4] = o;
    }
}

__global__ __launch_bounds__(128)
void attn_combine_kernel(const int* __restrict__ seqlens,
                         float* __restrict__ out)
{
    const int bh = blockIdx.x;          // b * HQ + hq
    const int b  = bh / HQ;
    const int hq = bh % HQ;
    const int h  = hq / G;
    const int g  = hq % G;
    const int d  = threadIdx.x;

    const int L   = seqlens[b];
    const int nsp = min(NS, (L + CHUNK - 1) / CHUNK);

    const int base = ((b * HKV + h) * NS) * G + g;  // + sp*G per split

    float M = NEG_BIG;
#pragma unroll 4
    for (int sp = 0; sp < nsp; sp++)
        M = fmaxf(M, g_part_m[base + sp * G]);

    // 2 independent accumulator pairs for MLP
    float L0 = 0.f, L1 = 0.f, o0 = 0.f, o1 = 0.f;
#pragma unroll 4
    for (int sp = 0; sp + 1 < nsp; sp += 2) {
        const int i0 = base + sp * G;
        const int i1 = base + (sp + 1) * G;
        const float e0 = exp2f(g_part_m[i0] - M);
        const float e1 = exp2f(g_part_m[i1] - M);
        L0 += e0 * g_part_l[i0];
        L1 += e1 * g_part_l[i1];
        o0 += e0 * g_part_acc[i0 * D + d];
        o1 += e1 * g_part_acc[i1 * D + d];
    }
    if (nsp & 1) {
        const int i0 = base + (nsp - 1) * G;
        const float e0 = exp2f(g_part_m[i0] - M);
        L0 += e0 * g_part_l[i0];
        o0 += e0 * g_part_acc[i0 * D + d];
    }

    out[bh * D + d] = (o0 + o1) / (L0 + L1);
}

extern "C" void kernel_launch(void* const* d_in, const int* in_sizes, int n_in,
                              void* d_out, int out_size)
{
    const float* q   = (const float*)d_in[0];
    const float* kc  = (const float*)d_in[1];
    const float* vc  = (const float*)d_in[2];
    const int*   sl  = (const int*)  d_in[3];
    const int*   bt  = (const int*)  d_in[4];
    float*       out = (float*)d_out;

    dim3 grid1(B, HKV, NS);
    attn_split_kernel<<<grid1, 256>>>(q, kc, vc, sl, bt);
    attn_combine_kernel<<<B * HQ, 128>>>(sl, out);
}

// round 4
// speedup vs baseline: 1.1791x; 1.1174x over previous
#include <cuda_runtime.h>
#include <cuda_pipeline.h>
#include <math.h>

// Problem constants (fixed by setup_inputs)
#define B       32
#define HQ      32
#define HKV     8
#define G       4      // HQ / HKV
#define D       128
#define BS      16     // block_size
#define MAXB    256    // max_blocks
#define CHUNK   64     // tokens per split
#define NS      64     // max splits = 4096 / CHUNK
#define NWARP   2
#define NTHR    (NWARP * 32)
#define ROWF    132    // padded K-row stride in floats (528B) -> conflict-free LDS

#define QSCALE  (0.08838834764831845f * 1.4426950408889634f)  // SCALE * log2(e)
#define NEG_BIG (-1e30f)
#define FULLM   0xffffffffu

// Scratch: partial (unnormalized) outputs + log-domain stats per (b, hkv, split, g)
__device__ float g_part_acc[B * HKV * NS * G * D];
__device__ float g_part_m  [B * HKV * NS * G];
__device__ float g_part_l  [B * HKV * NS * G];

__device__ __forceinline__ float warp_allmax(float v) {
    v = fmaxf(v, __shfl_xor_sync(FULLM, v, 16));
    v = fmaxf(v, __shfl_xor_sync(FULLM, v, 8));
    v = fmaxf(v, __shfl_xor_sync(FULLM, v, 4));
    v = fmaxf(v, __shfl_xor_sync(FULLM, v, 2));
    v = fmaxf(v, __shfl_xor_sync(FULLM, v, 1));
    return v;
}
__device__ __forceinline__ float warp_allsum(float v) {
    v += __shfl_xor_sync(FULLM, v, 16);
    v += __shfl_xor_sync(FULLM, v, 8);
    v += __shfl_xor_sync(FULLM, v, 4);
    v += __shfl_xor_sync(FULLM, v, 2);
    v += __shfl_xor_sync(FULLM, v, 1);
    return v;
}

__global__ __launch_bounds__(NTHR)
void attn_split_kernel(const float* __restrict__ q,
                       const float* __restrict__ kc,
                       const float* __restrict__ vc,
                       const int*   __restrict__ seqlens,
                       const int*   __restrict__ btab)
{
    extern __shared__ float smem[];
    float* qs   = smem;                         // G*D = 512 floats (pre-scaled q)
    float* Ks   = qs + G * D;                   // CHUNK * ROWF = 8448 floats
    float* ps   = Ks + CHUNK * ROWF;            // NWARP*32*4 = 256 floats
    float* smm  = ps + NWARP * 32 * 4;          // NWARP*G
    float* sml  = smm + NWARP * G;              // NWARP*G
    float* sma  = sml + NWARP * G;              // NWARP*G*D = 1024 floats

    const int b  = blockIdx.x;
    const int h  = blockIdx.y;
    const int sp = blockIdx.z;

    const int L     = seqlens[b];
    const int start = sp * CHUNK;
    if (start >= L) return;
    const int end = min(start + CHUNK, L);

    const int tid  = threadIdx.x;
    const int lane = tid & 31;
    const int w    = tid >> 5;

    // Blocks touched by this warp's 32 tokens (start, w*32 both 16-aligned)
    const int* bt   = btab + b * MAXB;
    const int  blkA = bt[(start >> 4) + w * 2];
    const int  blkB = bt[(start >> 4) + w * 2 + 1];

    // --- stage K tile: warp w stages rows [w*32, w*32+32); lane = 16B chunk ---
    {
        const float* kb0 = kc + ((blkA * BS) * HKV + h) * D + lane * 4;
        const float* kb1 = kc + ((blkB * BS) * HKV + h) * D + lane * 4;
        float* d0 = Ks + (w * 32) * ROWF + lane * 4;
#pragma unroll
        for (int r = 0; r < 16; r++)
            __pipeline_memcpy_async(d0 + r * ROWF, kb0 + r * (HKV * D), 16);
        float* d1 = Ks + (w * 32 + 16) * ROWF + lane * 4;
#pragma unroll
        for (int r = 0; r < 16; r++)
            __pipeline_memcpy_async(d1 + r * ROWF, kb1 + r * (HKV * D), 16);
        __pipeline_commit();
    }

    // --- stage q (pre-scaled), 128 float4 by 64 threads ---
    {
        const float4* qg = (const float4*)(q + (b * HQ + h * G) * D);
        float4* qd = (float4*)qs;
#pragma unroll
        for (int i = tid; i < G * D / 4; i += NTHR) {
            float4 v = qg[i];
            v.x *= QSCALE; v.y *= QSCALE; v.z *= QSCALE; v.w *= QSCALE;
            qd[i] = v;
        }
    }
    __syncthreads();                 // q visible to all
    __pipeline_wait_prior(0);        // own warp's K rows landed
    __syncwarp();

    float M0 = NEG_BIG, M1 = NEG_BIG, M2 = NEG_BIG, M3 = NEG_BIG;
    float l0 = 0.f, l1 = 0.f, l2 = 0.f, l3 = 0.f;
    float4 a0 = {0,0,0,0}, a1 = {0,0,0,0}, a2 = {0,0,0,0}, a3 = {0,0,0,0};

    const bool wvalid = (start + w * 32) < end;
    if (wvalid) {
        const int  myrow = w * 32 + lane;
        const bool valid = (start + myrow) < end;

        // --- scores: lane = token, dot over D from smem ---
        float s0 = 0.f, s1 = 0.f, s2 = 0.f, s3 = 0.f;
        const float4* krow = (const float4*)(Ks + myrow * ROWF);
        const float4* q4p  = (const float4*)qs;
#pragma unroll
        for (int c = 0; c < 32; c++) {
            const float4 k4 = krow[c];
            const float4 qa = q4p[c];
            const float4 qb = q4p[32 + c];
            const float4 qcc = q4p[64 + c];
            const float4 qd = q4p[96 + c];
            s0 += qa.x*k4.x + qa.y*k4.y + qa.z*k4.z + qa.w*k4.w;
            s1 += qb.x*k4.x + qb.y*k4.y + qb.z*k4.z + qb.w*k4.w;
            s2 += qcc.x*k4.x + qcc.y*k4.y + qcc.z*k4.z + qcc.w*k4.w;
            s3 += qd.x*k4.x + qd.y*k4.y + qd.z*k4.z + qd.w*k4.w;
        }
        if (!valid) { s0 = s1 = s2 = s3 = NEG_BIG; }

        // one max + one sum reduce per tile (not per token)
        M0 = warp_allmax(s0); M1 = warp_allmax(s1);
        M2 = warp_allmax(s2); M3 = warp_allmax(s3);

        const float p0 = exp2f(s0 - M0);   // invalid lanes -> exp2(-huge) = 0
        const float p1 = exp2f(s1 - M1);
        const float p2 = exp2f(s2 - M2);
        const float p3 = exp2f(s3 - M3);

        l0 = warp_allsum(p0); l1 = warp_allsum(p1);
        l2 = warp_allsum(p2); l3 = warp_allsum(p3);

        ((float4*)ps)[w * 32 + lane] = make_float4(p0, p1, p2, p3);
        __syncwarp();

        // --- PV: lanes own dims; V from GMEM coalesced, batched by 4 ---
        const float* vb0 = vc + ((blkA * BS) * HKV + h) * D + lane * 4;
        const float* vb1 = vc + ((blkB * BS) * HKV + h) * D + lane * 4;
        const float4* pw = (const float4*)ps + w * 32;
#pragma unroll
        for (int t0 = 0; t0 < 32; t0 += 4) {
            float4 v[4];
#pragma unroll
            for (int j = 0; j < 4; j++) {
                const int tt = t0 + j;
                const float* vb = (tt < 16) ? (vb0 + tt * (HKV * D))
                                            : (vb1 + (tt - 16) * (HKV * D));
                v[j] = *(const float4*)vb;
            }
#pragma unroll
            for (int j = 0; j < 4; j++) {
                const float4 pp = pw[t0 + j];
                a0.x += pp.x*v[j].x; a0.y += pp.x*v[j].y; a0.z += pp.x*v[j].z; a0.w += pp.x*v[j].w;
                a1.x += pp.y*v[j].x; a1.y += pp.y*v[j].y; a1.z += pp.y*v[j].z; a1.w += pp.y*v[j].w;
                a2.x += pp.z*v[j].x; a2.y += pp.z*v[j].y; a2.z += pp.z*v[j].z; a2.w += pp.z*v[j].w;
                a3.x += pp.w*v[j].x; a3.y += pp.w*v[j].y; a3.z += pp.w*v[j].z; a3.w += pp.w*v[j].w;
            }
        }
    }

    // --- write warp partials to smem ---
    if (lane == 0) {
        smm[w * G + 0] = M0; smm[w * G + 1] = M1; smm[w * G + 2] = M2; smm[w * G + 3] = M3;
        sml[w * G + 0] = l0; sml[w * G + 1] = l1; sml[w * G + 2] = l2; sml[w * G + 3] = l3;
    }
    ((float4*)(sma + (w * G + 0) * D))[lane] = a0;
    ((float4*)(sma + (w * G + 1) * D))[lane] = a1;
    ((float4*)(sma + (w * G + 2) * D))[lane] = a2;
    ((float4*)(sma + (w * G + 3) * D))[lane] = a3;
    __syncthreads();

    // --- merge 2 warps: warp w handles heads {2w, 2w+1} ---
#pragma unroll
    for (int k = 0; k < 2; k++) {
        const int gg = 2 * w + k;
        const float Ma = smm[0 * G + gg];
        const float Mb = smm[1 * G + gg];
        const float M  = fmaxf(Ma, Mb);
        const float e0 = exp2f(Ma - M);
        const float e1 = exp2f(Mb - M);
        const float Ls = e0 * sml[0 * G + gg] + e1 * sml[1 * G + gg];

        const float4 x0 = ((const float4*)(sma + (0 * G + gg) * D))[lane];
        const float4 x1 = ((const float4*)(sma + (1 * G + gg) * D))[lane];
        float4 o;
        o.x = e0 * x0.x + e1 * x1.x;
        o.y = e0 * x0.y + e1 * x1.y;
        o.z = e0 * x0.z + e1 * x1.z;
        o.w = e0 * x0.w + e1 * x1.w;

        const int idx = ((b * HKV + h) * NS + sp) * G + gg;
        if (lane == 0) {
            g_part_m[idx] = M;
            g_part_l[idx] = Ls;
        }
        ((float4*)(g_part_acc + idx * D))[lane] = o;
    }
}

__global__ __launch_bounds__(128)
void attn_combine_kernel(const int* __restrict__ seqlens,
                         float* __restrict__ out)
{
    const int bh = blockIdx.x;          // b * HQ + hq
    const int b  = bh / HQ;
    const int hq = bh % HQ;
    const int h  = hq / G;
    const int g  = hq % G;
    const int d  = threadIdx.x;

    const int L   = seqlens[b];
    const int nsp = min(NS, (L + CHUNK - 1) / CHUNK);

    const int base = ((b * HKV + h) * NS) * G + g;  // + sp*G per split

    float M = NEG_BIG;
#pragma unroll 4
    for (int sp = 0; sp < nsp; sp++)
        M = fmaxf(M, g_part_m[base + sp * G]);

    float L0 = 0.f, L1 = 0.f, o0 = 0.f, o1 = 0.f;
#pragma unroll 4
    for (int sp = 0; sp + 1 < nsp; sp += 2) {
        const int i0 = base + sp * G;
        const int i1 = base + (sp + 1) * G;
        const float e0 = exp2f(g_part_m[i0] - M);
        const float e1 = exp2f(g_part_m[i1] - M);
        L0 += e0 * g_part_l[i0];
        L1 += e1 * g_part_l[i1];
        o0 += e0 * g_part_acc[i0 * D + d];
        o1 += e1 * g_part_acc[i1 * D + d];
    }
    if (nsp & 1) {
        const int i0 = base + (nsp - 1) * G;
        const float e0 = exp2f(g_part_m[i0] - M);
        L0 += e0 * g_part_l[i0];
        o0 += e0 * g_part_acc[i0 * D + d];
    }

    out[bh * D + d] = (o0 + o1) / (L0 + L1);
}

extern "C" void kernel_launch(void* const* d_in, const int* in_sizes, int n_in,
                              void* d_out, int out_size)
{
    const float* q   = (const float*)d_in[0];
    const float* kc  = (const float*)d_in[1];
    const float* vc  = (const float*)d_in[2];
    const int*   sl  = (const int*)  d_in[3];
    const int*   bt  = (const int*)  d_in[4];
    float*       out = (float*)d_out;

    const int smem_bytes = (G * D + CHUNK * ROWF + NWARP * 32 * 4 +
                            NWARP * G * 2 + NWARP * G * D) * sizeof(float);

    dim3 grid1(B, HKV, NS);
    attn_split_kernel<<<grid1, NTHR, smem_bytes>>>(q, kc, vc, sl, bt);
    attn_combine_kernel<<<B * HQ, 128>>>(sl, out);
}

// round 6
// speedup vs baseline: 1.3027x; 1.1049x over previous
#include <cuda_runtime.h>
#include <cuda_pipeline.h>
#include <math.h>

// Problem constants (fixed by setup_inputs)
#define B       32
#define HQ      32
#define HKV     8
#define G       4      // HQ / HKV
#define D       128
#define BS      16     // block_size
#define MAXB    256    // max_blocks
#define CHUNK   64     // tokens per split
#define NS      64     // max splits = 4096 / CHUNK
#define NWARP   2
#define NTHR    (NWARP * 32)
#define ROWF    132    // padded K-row stride in floats (528B) -> conflict-free LDS

#define QSCALE  (0.08838834764831845f * 1.4426950408889634f)  // SCALE * log2(e)
#define NEG_BIG (-1e30f)
#define FULLM   0xffffffffu

// Scratch: partial (unnormalized) outputs + log-domain stats per (b, hkv, split, g)
__device__ float g_part_acc[B * HKV * NS * G * D];
__device__ float g_part_m  [B * HKV * NS * G];
__device__ float g_part_l  [B * HKV * NS * G];

__device__ __forceinline__ float warp_allmax(float v) {
    v = fmaxf(v, __shfl_xor_sync(FULLM, v, 16));
    v = fmaxf(v, __shfl_xor_sync(FULLM, v, 8));
    v = fmaxf(v, __shfl_xor_sync(FULLM, v, 4));
    v = fmaxf(v, __shfl_xor_sync(FULLM, v, 2));
    v = fmaxf(v, __shfl_xor_sync(FULLM, v, 1));
    return v;
}
__device__ __forceinline__ float warp_allsum(float v) {
    v += __shfl_xor_sync(FULLM, v, 16);
    v += __shfl_xor_sync(FULLM, v, 8);
    v += __shfl_xor_sync(FULLM, v, 4);
    v += __shfl_xor_sync(FULLM, v, 2);
    v += __shfl_xor_sync(FULLM, v, 1);
    return v;
}

__global__ __launch_bounds__(NTHR)
void attn_split_kernel(const float* __restrict__ q,
                       const float* __restrict__ kc,
                       const float* __restrict__ vc,
                       const int*   __restrict__ seqlens,
                       const int*   __restrict__ btab)
{
    extern __shared__ float smem[];
    float* qs   = smem;                         // G*D = 512 floats (pre-scaled q)
    float* Ks   = qs + G * D;                   // CHUNK * ROWF = 8448 floats
    float* ps   = Ks + CHUNK * ROWF;            // NWARP*32*4 = 256 floats
    float* smm  = ps + NWARP * 32 * 4;          // NWARP*G
    float* sml  = smm + NWARP * G;              // NWARP*G
    float* sma  = sml + NWARP * G;              // NWARP*G*D = 1024 floats

    const int b  = blockIdx.x;
    const int h  = blockIdx.y;
    const int sp = blockIdx.z;

    const int L     = seqlens[b];
    const int start = sp * CHUNK;
    if (start >= L) return;
    const int end = min(start + CHUNK, L);

    const int tid  = threadIdx.x;
    const int lane = tid & 31;
    const int w    = tid >> 5;

    // Blocks touched by this warp's 32 tokens (start, w*32 both 16-aligned)
    const int* bt   = btab + b * MAXB;
    const int  blkA = bt[(start >> 4) + w * 2];
    const int  blkB = bt[(start >> 4) + w * 2 + 1];

    // --- stage K tile: warp w stages rows [w*32, w*32+32); lane = 16B chunk ---
    {
        const float* kb0 = kc + ((blkA * BS) * HKV + h) * D + lane * 4;
        const float* kb1 = kc + ((blkB * BS) * HKV + h) * D + lane * 4;
        float* d0 = Ks + (w * 32) * ROWF + lane * 4;
#pragma unroll
        for (int r = 0; r < 16; r++)
            __pipeline_memcpy_async(d0 + r * ROWF, kb0 + r * (HKV * D), 16);
        float* d1 = Ks + (w * 32 + 16) * ROWF + lane * 4;
#pragma unroll
        for (int r = 0; r < 16; r++)
            __pipeline_memcpy_async(d1 + r * ROWF, kb1 + r * (HKV * D), 16);
        __pipeline_commit();
    }

    // --- stage q (pre-scaled), 128 float4 by 64 threads ---
    {
        const float4* qg = (const float4*)(q + (b * HQ + h * G) * D);
        float4* qd = (float4*)qs;
#pragma unroll
        for (int i = tid; i < G * D / 4; i += NTHR) {
            float4 v = qg[i];
            v.x *= QSCALE; v.y *= QSCALE; v.z *= QSCALE; v.w *= QSCALE;
            qd[i] = v;
        }
    }
    __syncthreads();                 // q visible to all
    __pipeline_wait_prior(0);        // own warp's K rows landed
    __syncwarp();

    float M0 = NEG_BIG, M1 = NEG_BIG, M2 = NEG_BIG, M3 = NEG_BIG;
    float l0 = 0.f, l1 = 0.f, l2 = 0.f, l3 = 0.f;
    float4 a0 = {0,0,0,0}, a1 = {0,0,0,0}, a2 = {0,0,0,0}, a3 = {0,0,0,0};

    const bool wvalid = (start + w * 32) < end;
    if (wvalid) {
        const int  myrow = w * 32 + lane;
        const bool valid = (start + myrow) < end;

        // --- scores: lane = token, dot over D from smem ---
        float s0 = 0.f, s1 = 0.f, s2 = 0.f, s3 = 0.f;
        const float4* krow = (const float4*)(Ks + myrow * ROWF);
        const float4* q4p  = (const float4*)qs;
#pragma unroll
        for (int c = 0; c < 32; c++) {
            const float4 k4 = krow[c];
            const float4 qa = q4p[c];
            const float4 qb = q4p[32 + c];
            const float4 qcc = q4p[64 + c];
            const float4 qd = q4p[96 + c];
            s0 += qa.x*k4.x + qa.y*k4.y + qa.z*k4.z + qa.w*k4.w;
            s1 += qb.x*k4.x + qb.y*k4.y + qb.z*k4.z + qb.w*k4.w;
            s2 += qcc.x*k4.x + qcc.y*k4.y + qcc.z*k4.z + qcc.w*k4.w;
            s3 += qd.x*k4.x + qd.y*k4.y + qd.z*k4.z + qd.w*k4.w;
        }
        if (!valid) { s0 = s1 = s2 = s3 = NEG_BIG; }

        // one max + one sum reduce per tile (not per token)
        M0 = warp_allmax(s0); M1 = warp_allmax(s1);
        M2 = warp_allmax(s2); M3 = warp_allmax(s3);

        const float p0 = exp2f(s0 - M0);   // invalid lanes -> exp2(-huge) = 0
        const float p1 = exp2f(s1 - M1);
        const float p2 = exp2f(s2 - M2);
        const float p3 = exp2f(s3 - M3);

        l0 = warp_allsum(p0); l1 = warp_allsum(p1);
        l2 = warp_allsum(p2); l3 = warp_allsum(p3);

        ((float4*)ps)[w * 32 + lane] = make_float4(p0, p1, p2, p3);
        __syncwarp();

        // --- PV: lanes own dims; V from GMEM coalesced, batched by 4 ---
        const float* vb0 = vc + ((blkA * BS) * HKV + h) * D + lane * 4;
        const float* vb1 = vc + ((blkB * BS) * HKV + h) * D + lane * 4;
        const float4* pw = (const float4*)ps + w * 32;
#pragma unroll
        for (int t0 = 0; t0 < 32; t0 += 4) {
            float4 v[4];
#pragma unroll
            for (int j = 0; j < 4; j++) {
                const int tt = t0 + j;
                const float* vb = (tt < 16) ? (vb0 + tt * (HKV * D))
                                            : (vb1 + (tt - 16) * (HKV * D));
                v[j] = *(const float4*)vb;
            }
#pragma unroll
            for (int j = 0; j < 4; j++) {
                const float4 pp = pw[t0 + j];
                a0.x += pp.x*v[j].x; a0.y += pp.x*v[j].y; a0.z += pp.x*v[j].z; a0.w += pp.x*v[j].w;
                a1.x += pp.y*v[j].x; a1.y += pp.y*v[j].y; a1.z += pp.y*v[j].z; a1.w += pp.y*v[j].w;
                a2.x += pp.z*v[j].x; a2.y += pp.z*v[j].y; a2.z += pp.z*v[j].z; a2.w += pp.z*v[j].w;
                a3.x += pp.w*v[j].x; a3.y += pp.w*v[j].y; a3.z += pp.w*v[j].z; a3.w += pp.w*v[j].w;
            }
        }
    }

    // --- write warp partials to smem ---
    if (lane == 0) {
        smm[w * G + 0] = M0; smm[w * G + 1] = M1; smm[w * G + 2] = M2; smm[w * G + 3] = M3;
        sml[w * G + 0] = l0; sml[w * G + 1] = l1; sml[w * G + 2] = l2; sml[w * G + 3] = l3;
    }
    ((float4*)(sma + (w * G + 0) * D))[lane] = a0;
    ((float4*)(sma + (w * G + 1) * D))[lane] = a1;
    ((float4*)(sma + (w * G + 2) * D))[lane] = a2;
    ((float4*)(sma + (w * G + 3) * D))[lane] = a3;
    __syncthreads();

    // --- merge 2 warps: warp w handles heads {2w, 2w+1} ---
#pragma unroll
    for (int k = 0; k < 2; k++) {
        const int gg = 2 * w + k;
        const float Ma = smm[0 * G + gg];
        const float Mb = smm[1 * G + gg];
        const float M  = fmaxf(Ma, Mb);
        const float e0 = exp2f(Ma - M);
        const float e1 = exp2f(Mb - M);
        const float Ls = e0 * sml[0 * G + gg] + e1 * sml[1 * G + gg];

        const float4 x0 = ((const float4*)(sma + (0 * G + gg) * D))[lane];
        const float4 x1 = ((const float4*)(sma + (1 * G + gg) * D))[lane];
        float4 o;
        o.x = e0 * x0.x + e1 * x1.x;
        o.y = e0 * x0.y + e1 * x1.y;
        o.z = e0 * x0.z + e1 * x1.z;
        o.w = e0 * x0.w + e1 * x1.w;

        const int idx = ((b * HKV + h) * NS + sp) * G + gg;
        if (lane == 0) {
            g_part_m[idx] = M;
            g_part_l[idx] = Ls;
        }
        ((float4*)(g_part_acc + idx * D))[lane] = o;
    }
}

// Combine: 512 threads = 4 split-lanes x 128 dims. Parallel over splits.
__global__ __launch_bounds__(512)
void attn_combine_kernel(const int* __restrict__ seqlens,
                         float* __restrict__ out)
{
    __shared__ float sM;
    __shared__ float sO[4][D];
    __shared__ float sL[4];

    const int bh = blockIdx.x;          // b * HQ + hq
    const int b  = bh / HQ;
    const int hq = bh % HQ;
    const int h  = hq / G;
    const int g  = hq % G;
    const int d  = threadIdx.x & (D - 1);
    const int s  = threadIdx.x >> 7;    // split lane 0..3
    const int lane = threadIdx.x & 31;

    const int L   = seqlens[b];
    const int nsp = min(NS, (L + CHUNK - 1) / CHUNK);

    const int base = ((b * HKV + h) * NS) * G + g;  // + sp*G per split

    // Phase 1: global max over splits (warp 0, parallel loads)
    if (threadIdx.x < 32) {
        float m1 = (lane      < nsp) ? g_part_m[base + lane * G]        : NEG_BIG;
        float m2 = (lane + 32 < nsp) ? g_part_m[base + (lane + 32) * G] : NEG_BIG;
        float m = warp_allmax(fmaxf(m1, m2));
        if (lane == 0) sM = m;
    }
    __syncthreads();
    const float M = sM;

    // Phase 2: each split-lane accumulates splits s, s+4, ... (2-deep MLP)
    float o0 = 0.f, o1 = 0.f, L0 = 0.f, L1 = 0.f;
    int sp = s;
    for (; sp + 4 < nsp; sp += 8) {
        const int i0 = base + sp * G;
        const int i1 = base + (sp + 4) * G;
        const float e0 = exp2f(g_part_m[i0] - M);
        const float e1 = exp2f(g_part_m[i1] - M);
        L0 += e0 * g_part_l[i0];
        L1 += e1 * g_part_l[i1];
        o0 += e0 * g_part_acc[i0 * D + d];
        o1 += e1 * g_part_acc[i1 * D + d];
    }
    if (sp < nsp) {
        const int i0 = base + sp * G;
        const float e0 = exp2f(g_part_m[i0] - M);
        L0 += e0 * g_part_l[i0];
        o0 += e0 * g_part_acc[i0 * D + d];
    }

    sO[s][d] = o0 + o1;
    if (d == 0) sL[s] = L0 + L1;
    __syncthreads();

    // Phase 3: reduce the 4 split-lanes, lane set s==0 writes out
    if (s == 0) {
        const float oT = sO[0][d] + sO[1][d] + sO[2][d] + sO[3][d];
        const float LT = sL[0] + sL[1] + sL[2] + sL[3];
        out[bh * D + d] = oT / LT;
    }
}

extern "C" void kernel_launch(void* const* d_in, const int* in_sizes, int n_in,
                              void* d_out, int out_size)
{
    const float* q   = (const float*)d_in[0];
    const float* kc  = (const float*)d_in[1];
    const float* vc  = (const float*)d_in[2];
    const int*   sl  = (const int*)  d_in[3];
    const int*   bt  = (const int*)  d_in[4];
    float*       out = (float*)d_out;

    const int smem_bytes = (G * D + CHUNK * ROWF + NWARP * 32 * 4 +
                            NWARP * G * 2 + NWARP * G * D) * sizeof(float);

    dim3 grid1(B, HKV, NS);
    attn_split_kernel<<<grid1, NTHR, smem_bytes>>>(q, kc, vc, sl, bt);
    attn_combine_kernel<<<B * HQ, 512>>>(sl, out);
}